// round 14
// baseline (speedup 1.0000x reference)
#include <cuda_runtime.h>
#include <cuda_fp16.h>
#include <stdint.h>
#include <math.h>

#define N_NODES 32768
#define N_EDGES 8192
#define ND 128
#define ED 128
#define HD 64
#define OD 128
#define NH 4
#define EPSV 1e-8f
#define ZERO_OFF (N_EDGES * 512)                 // byte offset of the zero pad row in g_te

// ---------------- scratch ----------------
__device__ __half g_te[((size_t)N_EDGES + 1) * 256];   // +1 zero pad row
__device__ __half g_agg[(size_t)N_NODES * 256];
__device__ __half g_nodeWh[NH * ND * HD];
__device__ __half g_outWh[NH * HD * OD];
__device__ float  g_bufA[(size_t)N_NODES * OD];
__device__ float  g_bufB[(size_t)N_NODES * OD];
__device__ float  g_cmin[NH * OD];
__device__ float  g_cmax[NH * OD];

// ---------------- helpers ----------------
__device__ __forceinline__ void atomicMinF(float* addr, float value) {
    if (value >= 0.f) atomicMin((int*)addr, __float_as_int(value));
    else              atomicMax((unsigned int*)addr, __float_as_uint(value));
}
__device__ __forceinline__ void atomicMaxF(float* addr, float value) {
    if (value >= 0.f) atomicMax((int*)addr, __float_as_int(value));
    else              atomicMin((unsigned int*)addr, __float_as_uint(value));
}
__device__ __forceinline__ unsigned smem_u32(const void* p) {
    return (unsigned)__cvta_generic_to_shared(p);
}
__device__ __forceinline__ void ldm_x4(unsigned addr, unsigned& r0, unsigned& r1,
                                       unsigned& r2, unsigned& r3) {
    asm volatile("ldmatrix.sync.aligned.m8n8.x4.shared.b16 {%0,%1,%2,%3}, [%4];"
                 : "=r"(r0), "=r"(r1), "=r"(r2), "=r"(r3) : "r"(addr));
}
__device__ __forceinline__ void ldm_x4t(unsigned addr, unsigned& r0, unsigned& r1,
                                        unsigned& r2, unsigned& r3) {
    asm volatile("ldmatrix.sync.aligned.m8n8.x4.trans.shared.b16 {%0,%1,%2,%3}, [%4];"
                 : "=r"(r0), "=r"(r1), "=r"(r2), "=r"(r3) : "r"(addr));
}
__device__ __forceinline__ void mma16816(float& c0, float& c1, float& c2, float& c3,
                                         unsigned a0, unsigned a1, unsigned a2, unsigned a3,
                                         unsigned b0, unsigned b1) {
    asm volatile("mma.sync.aligned.m16n8k16.row.col.f32.f16.f16.f32 "
                 "{%0,%1,%2,%3},{%4,%5,%6,%7},{%8,%9},{%0,%1,%2,%3};"
                 : "+f"(c0), "+f"(c1), "+f"(c2), "+f"(c3)
                 : "r"(a0), "r"(a1), "r"(a2), "r"(a3), "r"(b0), "r"(b1));
}
__device__ __forceinline__ unsigned pack2(float a, float b) {
    __half2 h = __floats2half2_rn(a, b);
    return *(unsigned*)&h;
}
__device__ __forceinline__ void split2(float a, float b, unsigned& hi, unsigned& lo) {
    __half ha = __float2half(a), hb = __float2half(b);
    __half la = __float2half(a - __half2float(ha));
    __half lb = __float2half(b - __half2float(hb));
    __half2 h = __halves2half2(ha, hb), l = __halves2half2(la, lb);
    hi = *(unsigned*)&h; lo = *(unsigned*)&l;
}
// packed fp32 add (exact): acc += cvt(h2) using one add.rn.f32x2
__device__ __forceinline__ void padd2(float2& acc, unsigned h2bits) {
    float2 f = __half22float2(*(__half2*)&h2bits);
    asm("add.rn.f32x2 %0, %0, %1;"
        : "+l"(*reinterpret_cast<unsigned long long*>(&acc))
        : "l"(*reinterpret_cast<const unsigned long long*>(&f)));
}
__device__ __forceinline__ void paddf(float2& acc, float2 f) {
    asm("add.rn.f32x2 %0, %0, %1;"
        : "+l"(*reinterpret_cast<unsigned long long*>(&acc))
        : "l"(*reinterpret_cast<const unsigned long long*>(&f)));
}

// ---------------- kernel 0: init + zero te pad row ----------------
__global__ void init_minmax_kernel(float* cmin, float* cmax, __half* te) {
    int t = threadIdx.x;
    cmin[t] =  __int_as_float(0x7f800000);
    cmax[t] = -__int_as_float(0x7f800000);
    if (t < 32)
        ((uint4*)((char*)te + ZERO_OFF))[t] = make_uint4(0u, 0u, 0u, 0u);
}
__global__ void cvt_w_kernel(const float* __restrict__ nodeW, const float* __restrict__ outW,
                             __half* __restrict__ nodeWh, __half* __restrict__ outWh) {
    int i = blockIdx.x * 256 + threadIdx.x;
    nodeWh[i] = __float2half(nodeW[i]);
    outWh[i]  = __float2half(outW[i]);
}

// ---------------- kernel 1: te via HMMA hi/lo split (R9 proven) ----------------
__global__ __launch_bounds__(256, 1) void te_mma_kernel(
    const float* __restrict__ ef, const float* __restrict__ edgeW,
    const float* __restrict__ edgeB, __half* __restrict__ te) {
    extern __shared__ char smc[];
    __half* sefH = (__half*)(smc);
    __half* sefL = (__half*)(smc + 34816);
    __half* sWH  = (__half*)(smc + 69632);
    __half* sWL  = (__half*)(smc + 137216);

    int t = threadIdx.x, lane = t & 31, w = t >> 5;
    int e0 = blockIdx.x * 128;
    {
        int qg = lane * 4;
#pragma unroll
        for (int i = 0; i < 16; i++) {
            int r = i * 8 + w;
            float4 v = __ldg((const float4*)&ef[(size_t)(e0 + r) * ED + qg]);
            unsigned h0, l0, h1, l1;
            split2(v.x, v.y, h0, l0);
            split2(v.z, v.w, h1, l1);
            *(uint2*)&sefH[r * 136 + qg] = make_uint2(h0, h1);
            *(uint2*)&sefL[r * 136 + qg] = make_uint2(l0, l1);
        }
    }
    {
#pragma unroll
        for (int i = 0; i < 32; i++) {
            int idx4 = i * 256 + t;
            int fidx = idx4 * 4;
            int h = fidx >> 13, k = (fidx >> 6) & 127, c = fidx & 63;
            int n = h * 64 + c;
            float4 v = __ldg((const float4*)&edgeW[fidx]);
            unsigned h0, l0, h1, l1;
            split2(v.x, v.y, h0, l0);
            split2(v.z, v.w, h1, l1);
            *(uint2*)&sWH[k * 264 + n] = make_uint2(h0, h1);
            *(uint2*)&sWL[k * 264 + n] = make_uint2(l0, l1);
        }
    }
    __syncthreads();

    int mw = w >> 2, nwp = w & 3;
    int g = lane >> 2, tig = lane & 3;
    int m0 = mw * 64, nb = nwp * 64;
    const __half* aP[3] = { sefH, sefH, sefL };
    const __half* bP[3] = { sWH,  sWL,  sWH  };

#pragma unroll
    for (int msub = 0; msub < 64; msub += 16) {
        float acc[8][4];
#pragma unroll
        for (int j = 0; j < 8; j++)
#pragma unroll
            for (int q = 0; q < 4; q++) acc[j][q] = 0.f;
#pragma unroll
        for (int pass = 0; pass < 3; pass++) {
            unsigned aBase = smem_u32(aP[pass]) +
                (unsigned)(((m0 + msub + (lane & 15)) * 136 + (lane >> 4) * 8) * 2);
            unsigned bBase = smem_u32(bP[pass]) +
                (unsigned)((((lane & 15)) * 264 + nb + (lane >> 4) * 8) * 2);
#pragma unroll
            for (int kk = 0; kk < 8; kk++) {
                int k0 = kk * 16;
                unsigned a0, a1, a2, a3;
                ldm_x4(aBase + k0 * 2, a0, a1, a2, a3);
#pragma unroll
                for (int s2 = 0; s2 < 4; s2++) {
                    unsigned b0, b1, b2, b3;
                    ldm_x4t(bBase + (k0 * 264 + s2 * 16) * 2, b0, b1, b2, b3);
                    mma16816(acc[s2 * 2][0], acc[s2 * 2][1], acc[s2 * 2][2], acc[s2 * 2][3],
                             a0, a1, a2, a3, b0, b1);
                    mma16816(acc[s2 * 2 + 1][0], acc[s2 * 2 + 1][1], acc[s2 * 2 + 1][2],
                             acc[s2 * 2 + 1][3], a0, a1, a2, a3, b2, b3);
                }
            }
        }
#pragma unroll
        for (int j = 0; j < 8; j++) {
            int cb = nb + j * 8 + tig * 2;
            float b0 = __ldg(&edgeB[cb]);
            float b1 = __ldg(&edgeB[cb + 1]);
            int r0 = e0 + m0 + msub + g;
            *(__half2*)&te[(size_t)r0 * 256 + cb] =
                __floats2half2_rn(acc[j][0] + b0, acc[j][1] + b1);
            *(__half2*)&te[(size_t)(r0 + 8) * 256 + cb] =
                __floats2half2_rn(acc[j][2] + b0, acc[j][3] + b1);
        }
    }
}

// ---------------- kernel 2: scan — uint4 gather (8 groups x 32 cols) ----------------
// s_idx byte offsets, padded to 32-int multiple (zero row). Each thread owns 16B of
// the te row -> one LDG.128 per gathered row per thread. LDS.128 index batching.
__global__ void scan_kernel(const float* __restrict__ inc, const __half* __restrict__ te,
                            __half* __restrict__ agg) {
    __shared__ int s_idx[544];
    __shared__ int s_wcnt[8];
    __shared__ float4 sxch[448];                  // 7 groups x 32 cols x 2 float4
    int t = threadIdx.x, w = t >> 5, l = t & 31;
    int n = blockIdx.x;

    const float4* row = (const float4*)(inc + (size_t)n * N_EDGES);
    unsigned mask = 0u;
#pragma unroll
    for (int i = 0; i < 8; i++) {
        float4 v = __ldcs(row + i * 256 + t);
        unsigned m = (v.x != 0.f ? 1u : 0u) | (v.y != 0.f ? 2u : 0u) |
                     (v.z != 0.f ? 4u : 0u) | (v.w != 0.f ? 8u : 0u);
        mask |= m << (i * 4);
    }
    int myc = __popc(mask);
    int pre = myc;
#pragma unroll
    for (int d = 1; d < 32; d <<= 1) {
        int o = __shfl_up_sync(0xffffffffu, pre, d);
        if (l >= d) pre += o;
    }
    int wtot = __shfl_sync(0xffffffffu, pre, 31);
    int myoff = pre - myc;
    if (l == 0) s_wcnt[w] = wtot;
    __syncthreads();

    int base = 0, cnt = 0;
#pragma unroll
    for (int w2 = 0; w2 < 8; w2++) {
        int c2 = s_wcnt[w2];
        if (w2 < w) base += c2;
        cnt += c2;
    }
    int pos = base + myoff;
    unsigned mm = mask;
    while (mm) {
        int b = __ffs(mm) - 1;
        mm &= mm - 1;
        s_idx[pos++] = (((b >> 2) * 256 + t) * 4 + (b & 3)) << 9;  // byte offset
    }
    int qs = ((cnt + 31) >> 5) << 2;              // ints per group (8 groups), mult of 4
    int padTot = qs * 8;
    if (t < padTot - cnt) s_idx[cnt + t] = ZERO_OFF;   // pad (<32 entries) -> zero row
    __syncthreads();

    float inv = 1.f / ((float)cnt + EPSV);

    // gather: group q (0..7) owns contiguous chunk [q*qs, (q+1)*qs); 32 col-threads x 16B
    int q = t >> 5, c8 = t & 31;
    const char* teB = (const char*)te + c8 * 16;
    float2 aA[4], aB[4];
#pragma unroll
    for (int j = 0; j < 4; j++) { aA[j] = make_float2(0.f, 0.f); aB[j] = make_float2(0.f, 0.f); }
    int mEnd = q * qs + qs;
    for (int m = q * qs; m < mEnd; m += 4) {
        int4 ix = *(const int4*)&s_idx[m];        // one LDS.128 = 4 byte-offsets
        uint4 v0 = __ldg((const uint4*)(teB + ix.x));
        uint4 v1 = __ldg((const uint4*)(teB + ix.y));
        uint4 v2 = __ldg((const uint4*)(teB + ix.z));
        uint4 v3 = __ldg((const uint4*)(teB + ix.w));
        padd2(aA[0], v0.x); padd2(aA[1], v0.y); padd2(aA[2], v0.z); padd2(aA[3], v0.w);
        padd2(aB[0], v1.x); padd2(aB[1], v1.y); padd2(aB[2], v1.z); padd2(aB[3], v1.w);
        padd2(aA[0], v2.x); padd2(aA[1], v2.y); padd2(aA[2], v2.z); padd2(aA[3], v2.w);
        padd2(aB[0], v3.x); padd2(aB[1], v3.y); padd2(aB[2], v3.z); padd2(aB[3], v3.w);
    }
#pragma unroll
    for (int j = 0; j < 4; j++) paddf(aA[j], aB[j]);
    __syncthreads();
    if (q != 0) {
        sxch[(q - 1) * 64 + c8 * 2]     = make_float4(aA[0].x, aA[0].y, aA[1].x, aA[1].y);
        sxch[(q - 1) * 64 + c8 * 2 + 1] = make_float4(aA[2].x, aA[2].y, aA[3].x, aA[3].y);
    }
    __syncthreads();
    if (q == 0) {
        float4 lo = make_float4(aA[0].x, aA[0].y, aA[1].x, aA[1].y);
        float4 hi = make_float4(aA[2].x, aA[2].y, aA[3].x, aA[3].y);
#pragma unroll
        for (int g2 = 0; g2 < 7; g2++) {
            float4 blo = sxch[g2 * 64 + c8 * 2];
            float4 bhi = sxch[g2 * 64 + c8 * 2 + 1];
            lo.x += blo.x; lo.y += blo.y; lo.z += blo.z; lo.w += blo.w;
            hi.x += bhi.x; hi.y += bhi.y; hi.z += bhi.z; hi.w += bhi.w;
        }
        lo.x *= inv; lo.y *= inv; lo.z *= inv; lo.w *= inv;
        hi.x *= inv; hi.y *= inv; hi.z *= inv; hi.w *= inv;
        *(uint4*)&agg[(size_t)n * 256 + c8 * 8] =
            make_uint4(pack2(lo.x, lo.y), pack2(lo.z, lo.w),
                       pack2(hi.x, hi.y), pack2(hi.z, hi.w));
    }
}

// ---------------- kernel 3: HMMA fused head (R7/R9 proven) ----------------
__global__ __launch_bounds__(256, 2) void head_kernel(
    const float* __restrict__ x, const __half* __restrict__ agg,
    const __half* __restrict__ nodeWh, const float* __restrict__ nodeB,
    const float* __restrict__ attnW, const float* __restrict__ attnB,
    const __half* __restrict__ outWh, const float* __restrict__ outB,
    int h, float* __restrict__ upd,
    float* __restrict__ cmin, float* __restrict__ cmax,
    const float* __restrict__ pmin, const float* __restrict__ pmax) {
    extern __shared__ char smc[];
    __half* sxh  = (__half*)(smc);
    __half* swh  = (__half*)(smc + 34816);
    __half* stn  = (__half*)(smc + 53248);
    __half* sagg = (__half*)(smc + 71680);
    float* sattn = (float*)(smc + 90112);
    float* sg    = (float*)(smc + 90368);
    float* smin  = (float*)(smc + 90880);
    float* smax  = (float*)(smc + 92928);

    int t = threadIdx.x, lane = t & 31, w = t >> 5;
    int n0 = blockIdx.x * 128;
    bool dn = (pmin != nullptr);

    {
        int qg = lane * 4;
        float sa4[4], sb4[4];
        if (dn) {
#pragma unroll
            for (int j = 0; j < 4; j++) {
                float mn = __ldg(&pmin[qg + j]), mx = __ldg(&pmax[qg + j]);
                sb4[j] = mn; sa4[j] = 1.f / (mx - mn + EPSV);
            }
        }
#pragma unroll
        for (int i = 0; i < 16; i++) {
            int r = i * 8 + w;
            float4 v = __ldg((const float4*)&x[(size_t)(n0 + r) * ND + qg]);
            if (dn) {
                v.x = fmaxf(0.f, (v.x - sb4[0]) * sa4[0]);
                v.y = fmaxf(0.f, (v.y - sb4[1]) * sa4[1]);
                v.z = fmaxf(0.f, (v.z - sb4[2]) * sa4[2]);
                v.w = fmaxf(0.f, (v.w - sb4[3]) * sa4[3]);
            }
            *(uint2*)&sxh[r * 136 + qg] = make_uint2(pack2(v.x, v.y), pack2(v.z, v.w));
        }
    }
    {
        const __half* nw = nodeWh + h * (ND * HD);
#pragma unroll
        for (int i = 0; i < 4; i++) {
            int idx = i * 256 + t;
            int k = idx >> 3, n8 = (idx & 7) * 8;
            *(uint4*)&swh[k * 72 + n8] = __ldg((const uint4*)&nw[idx * 8]);
        }
    }
    {
        int c8 = (t & 7) * 8;
#pragma unroll
        for (int i = 0; i < 4; i++) {
            int r = i * 32 + (t >> 3);
            *(uint4*)&sagg[r * 72 + c8] =
                __ldg((const uint4*)&agg[(size_t)(n0 + r) * 256 + h * 64 + c8]);
        }
    }
    if (t < 64) sattn[t] = attnW[h * 64 + t];
    __syncthreads();

    int mw = w >> 1, nwp = w & 1;
    int g = lane >> 2, tig = lane & 3;

    {
        int m0 = mw * 32, nb = nwp * 32;
#pragma unroll
        for (int msub = 0; msub < 32; msub += 16) {
            float acc[4][4];
#pragma unroll
            for (int j = 0; j < 4; j++)
#pragma unroll
                for (int q = 0; q < 4; q++) acc[j][q] = 0.f;

            unsigned aBase = smem_u32(sxh) +
                (unsigned)(((m0 + msub + (lane & 15)) * 136 + (lane >> 4) * 8) * 2);
            unsigned bBase = smem_u32(swh) +
                (unsigned)((((lane & 15)) * 72 + nb + (lane >> 4) * 8) * 2);
#pragma unroll
            for (int kk = 0; kk < 8; kk++) {
                int k0 = kk * 16;
                unsigned a0, a1, a2, a3, b0, b1, b2, b3, b4, b5, b6, b7;
                ldm_x4(aBase + k0 * 2, a0, a1, a2, a3);
                ldm_x4t(bBase + k0 * 72 * 2, b0, b1, b2, b3);
                ldm_x4t(bBase + k0 * 72 * 2 + 32, b4, b5, b6, b7);
                mma16816(acc[0][0], acc[0][1], acc[0][2], acc[0][3], a0, a1, a2, a3, b0, b1);
                mma16816(acc[1][0], acc[1][1], acc[1][2], acc[1][3], a0, a1, a2, a3, b2, b3);
                mma16816(acc[2][0], acc[2][1], acc[2][2], acc[2][3], a0, a1, a2, a3, b4, b5);
                mma16816(acc[3][0], acc[3][1], acc[3][2], acc[3][3], a0, a1, a2, a3, b6, b7);
            }
#pragma unroll
            for (int j = 0; j < 4; j++) {
                int cb = nb + j * 8 + tig * 2;
                float nb0 = __ldg(&nodeB[h * 64 + cb]);
                float nb1 = __ldg(&nodeB[h * 64 + cb + 1]);
                int rr = m0 + msub + g;
                stn[rr * 72 + cb]           = __float2half(acc[j][0] + nb0);
                stn[rr * 72 + cb + 1]       = __float2half(acc[j][1] + nb1);
                stn[(rr + 8) * 72 + cb]     = __float2half(acc[j][2] + nb0);
                stn[(rr + 8) * 72 + cb + 1] = __float2half(acc[j][3] + nb1);
            }
        }
    }
    __syncthreads();

    {
        int r = w * 16 + (lane >> 1);
        int sub = lane & 1;
        float s = 0.f;
#pragma unroll
        for (int cc = 0; cc < 32; cc++) {
            int c = sub * 32 + cc;
            s += (__half2float(stn[r * 72 + c]) + __half2float(sagg[r * 72 + c])) * sattn[c];
        }
        s += __shfl_xor_sync(0xffffffffu, s, 1);
        if (sub == 0) {
            s += attnB[h];
            s = (s >= 0.f) ? s : 0.2f * s;
            sg[r] = 1.f / (1.f + expf(-s));
        }
    }
    {
        const __half* ow = outWh + h * (HD * OD);
#pragma unroll
        for (int i = 0; i < 4; i++) {
            int idx = i * 256 + t;
            int k = idx >> 4, n8 = (idx & 15) * 8;
            *(uint4*)&swh[k * 136 + n8] = __ldg((const uint4*)&ow[idx * 8]);
        }
    }
    __syncthreads();

#pragma unroll
    for (int i = 0; i < 16; i++) {
        int L = i * 256 + t;
        int r = L >> 5, c2 = (L & 31) * 2;
        float gv = sg[r];
        float2 av = __half22float2(*(__half2*)&sagg[r * 72 + c2]);
        float2 tv = __half22float2(*(__half2*)&stn[r * 72 + c2]);
        *(__half2*)&stn[r * 72 + c2] = __floats2half2_rn(gv * av.x + tv.x, gv * av.y + tv.y);
    }
    __syncthreads();

    {
        int m0 = mw * 32, nb = nwp * 64;
        float mnA[8], mxA[8], mnB[8], mxB[8];
#pragma unroll
        for (int j = 0; j < 8; j++) {
            mnA[j] = 3.4e38f; mxA[j] = -3.4e38f;
            mnB[j] = 3.4e38f; mxB[j] = -3.4e38f;
        }
#pragma unroll
        for (int msub = 0; msub < 32; msub += 16) {
            float acc[8][4];
#pragma unroll
            for (int j = 0; j < 8; j++)
#pragma unroll
                for (int q = 0; q < 4; q++) acc[j][q] = 0.f;

            unsigned aBase = smem_u32(stn) +
                (unsigned)(((m0 + msub + (lane & 15)) * 72 + (lane >> 4) * 8) * 2);
            unsigned bBase = smem_u32(swh) +
                (unsigned)((((lane & 15)) * 136 + nb + (lane >> 4) * 8) * 2);
#pragma unroll
            for (int kk = 0; kk < 4; kk++) {
                int k0 = kk * 16;
                unsigned a0, a1, a2, a3;
                ldm_x4(aBase + k0 * 2, a0, a1, a2, a3);
#pragma unroll
                for (int s2 = 0; s2 < 4; s2++) {
                    unsigned b0, b1, b2, b3;
                    ldm_x4t(bBase + (k0 * 136 + s2 * 16) * 2, b0, b1, b2, b3);
                    mma16816(acc[s2 * 2][0], acc[s2 * 2][1], acc[s2 * 2][2], acc[s2 * 2][3],
                             a0, a1, a2, a3, b0, b1);
                    mma16816(acc[s2 * 2 + 1][0], acc[s2 * 2 + 1][1], acc[s2 * 2 + 1][2],
                             acc[s2 * 2 + 1][3], a0, a1, a2, a3, b2, b3);
                }
            }
#pragma unroll
            for (int j = 0; j < 8; j++) {
                int cb = nb + j * 8 + tig * 2;
                float ob0 = __ldg(&outB[h * 128 + cb]);
                float ob1 = __ldg(&outB[h * 128 + cb + 1]);
                float o00 = acc[j][0] + ob0, o01 = acc[j][1] + ob1;
                float o10 = acc[j][2] + ob0, o11 = acc[j][3] + ob1;
                int r0g = n0 + m0 + msub + g;
                *(float2*)&upd[(size_t)r0g * OD + cb]       = make_float2(o00, o01);
                *(float2*)&upd[(size_t)(r0g + 8) * OD + cb] = make_float2(o10, o11);
                mnA[j] = fminf(mnA[j], fminf(o00, o10)); mxA[j] = fmaxf(mxA[j], fmaxf(o00, o10));
                mnB[j] = fminf(mnB[j], fminf(o01, o11)); mxB[j] = fmaxf(mxB[j], fmaxf(o01, o11));
            }
        }
#pragma unroll
        for (int d = 4; d <= 16; d <<= 1) {
#pragma unroll
            for (int j = 0; j < 8; j++) {
                mnA[j] = fminf(mnA[j], __shfl_xor_sync(0xffffffffu, mnA[j], d));
                mxA[j] = fmaxf(mxA[j], __shfl_xor_sync(0xffffffffu, mxA[j], d));
                mnB[j] = fminf(mnB[j], __shfl_xor_sync(0xffffffffu, mnB[j], d));
                mxB[j] = fmaxf(mxB[j], __shfl_xor_sync(0xffffffffu, mxB[j], d));
            }
        }
        if (lane < 4) {
#pragma unroll
            for (int j = 0; j < 8; j++) {
                int cb = nb + j * 8 + tig * 2;
                smin[mw * 128 + cb]     = mnA[j];
                smin[mw * 128 + cb + 1] = mnB[j];
                smax[mw * 128 + cb]     = mxA[j];
                smax[mw * 128 + cb + 1] = mxB[j];
            }
        }
    }
    __syncthreads();
    if (t < 128) {
        float m = smin[t], M = smax[t];
#pragma unroll
        for (int r = 1; r < 4; r++) {
            m = fminf(m, smin[r * 128 + t]);
            M = fmaxf(M, smax[r * 128 + t]);
        }
        atomicMinF(&cmin[t], m);
        atomicMaxF(&cmax[t], M);
    }
}

// ---------------- kernel 4: final norm ----------------
__global__ void norm_kernel(const float4* __restrict__ upd, const float* __restrict__ cmin,
                            const float* __restrict__ cmax, float4* __restrict__ dst) {
    __shared__ float sa[128], sb[128];
    int t = threadIdx.x;
    if (t < 128) {
        float mn = cmin[t], mx = cmax[t];
        sa[t] = 1.f / (mx - mn + EPSV);
        sb[t] = mn;
    }
    __syncthreads();
    int i = blockIdx.x * 256 + t;
    float4 v = upd[i];
    int c = (i & 31) * 4;
    float4 o;
    o.x = fmaxf(0.f, (v.x - sb[c + 0]) * sa[c + 0]);
    o.y = fmaxf(0.f, (v.y - sb[c + 1]) * sa[c + 1]);
    o.z = fmaxf(0.f, (v.z - sb[c + 2]) * sa[c + 2]);
    o.w = fmaxf(0.f, (v.w - sb[c + 3]) * sa[c + 3]);
    dst[i] = o;
}

// ---------------- launch ----------------
extern "C" void kernel_launch(void* const* d_in, const int* in_sizes, int n_in,
                              void* d_out, int out_size) {
    const float* nodeF = (const float*)d_in[0];
    const float* inc   = (const float*)d_in[1];
    const float* edgeF = (const float*)d_in[2];
    const float* nodeW = (const float*)d_in[3];
    const float* nodeB = (const float*)d_in[4];
    const float* edgeW = (const float*)d_in[5];
    const float* edgeB = (const float*)d_in[6];
    const float* attnW = (const float*)d_in[7];
    const float* attnB = (const float*)d_in[8];
    const float* outW  = (const float*)d_in[9];
    const float* outB  = (const float*)d_in[10];

    __half *te, *agg, *nodeWh, *outWh;  float *bufA, *bufB, *cmin, *cmax;
    cudaGetSymbolAddress((void**)&te,     g_te);
    cudaGetSymbolAddress((void**)&agg,    g_agg);
    cudaGetSymbolAddress((void**)&nodeWh, g_nodeWh);
    cudaGetSymbolAddress((void**)&outWh,  g_outWh);
    cudaGetSymbolAddress((void**)&bufA,   g_bufA);
    cudaGetSymbolAddress((void**)&bufB,   g_bufB);
    cudaGetSymbolAddress((void**)&cmin,   g_cmin);
    cudaGetSymbolAddress((void**)&cmax,   g_cmax);

    const int hk_smem = 94976;
    const int te_smem = 204800;
    cudaFuncSetAttribute(head_kernel, cudaFuncAttributeMaxDynamicSharedMemorySize, hk_smem);
    cudaFuncSetAttribute(te_mma_kernel, cudaFuncAttributeMaxDynamicSharedMemorySize, te_smem);

    init_minmax_kernel<<<1, NH * OD>>>(cmin, cmax, te);
    cvt_w_kernel<<<NH * ND * HD / 256, 256>>>(nodeW, outW, nodeWh, outWh);
    te_mma_kernel<<<N_EDGES / 128, 256, te_smem>>>(edgeF, edgeW, edgeB, te);
    scan_kernel<<<N_NODES, 256>>>(inc, te, agg);

    float* bufs[2] = { bufA, bufB };
    const float* xin = nodeF;
    for (int h = 0; h < NH; h++) {
        float* dst = bufs[h & 1];
        const float* pmin = (h == 0) ? nullptr : cmin + (h - 1) * 128;
        const float* pmax = (h == 0) ? nullptr : cmax + (h - 1) * 128;
        head_kernel<<<N_NODES / 128, 256, hk_smem>>>(xin, agg, nodeWh, nodeB, attnW, attnB,
                                                     outWh, outB, h, dst,
                                                     cmin + h * 128, cmax + h * 128,
                                                     pmin, pmax);
        xin = dst;
    }
    norm_kernel<<<(N_NODES * OD / 4) / 256, 256>>>((const float4*)bufs[(NH - 1) & 1],
                                                   cmin + (NH - 1) * 128, cmax + (NH - 1) * 128,
                                                   (float4*)d_out);
}

// round 16
// speedup vs baseline: 1.0237x; 1.0237x over previous
#include <cuda_runtime.h>
#include <cuda_fp16.h>
#include <stdint.h>
#include <math.h>

#define N_NODES 32768
#define N_EDGES 8192
#define ND 128
#define ED 128
#define HD 64
#define OD 128
#define NH 4
#define EPSV 1e-8f
#define ZERO_OFF (N_EDGES * 512)                 // byte offset of the zero pad row in g_te

// ---------------- scratch ----------------
__device__ __half g_te[((size_t)N_EDGES + 1) * 256];   // +1 zero pad row
__device__ __half g_agg[(size_t)N_NODES * 256];
__device__ __half g_nodeWh[NH * ND * HD];
__device__ __half g_outWh[NH * HD * OD];
__device__ float  g_bufA[(size_t)N_NODES * OD];
__device__ float  g_bufB[(size_t)N_NODES * OD];
__device__ float  g_cmin[NH * OD];
__device__ float  g_cmax[NH * OD];

// ---------------- helpers ----------------
__device__ __forceinline__ void atomicMinF(float* addr, float value) {
    if (value >= 0.f) atomicMin((int*)addr, __float_as_int(value));
    else              atomicMax((unsigned int*)addr, __float_as_uint(value));
}
__device__ __forceinline__ void atomicMaxF(float* addr, float value) {
    if (value >= 0.f) atomicMax((int*)addr, __float_as_int(value));
    else              atomicMin((unsigned int*)addr, __float_as_uint(value));
}
__device__ __forceinline__ unsigned smem_u32(const void* p) {
    return (unsigned)__cvta_generic_to_shared(p);
}
__device__ __forceinline__ void ldm_x4(unsigned addr, unsigned& r0, unsigned& r1,
                                       unsigned& r2, unsigned& r3) {
    asm volatile("ldmatrix.sync.aligned.m8n8.x4.shared.b16 {%0,%1,%2,%3}, [%4];"
                 : "=r"(r0), "=r"(r1), "=r"(r2), "=r"(r3) : "r"(addr));
}
__device__ __forceinline__ void ldm_x4t(unsigned addr, unsigned& r0, unsigned& r1,
                                        unsigned& r2, unsigned& r3) {
    asm volatile("ldmatrix.sync.aligned.m8n8.x4.trans.shared.b16 {%0,%1,%2,%3}, [%4];"
                 : "=r"(r0), "=r"(r1), "=r"(r2), "=r"(r3) : "r"(addr));
}
__device__ __forceinline__ void mma16816(float& c0, float& c1, float& c2, float& c3,
                                         unsigned a0, unsigned a1, unsigned a2, unsigned a3,
                                         unsigned b0, unsigned b1) {
    asm volatile("mma.sync.aligned.m16n8k16.row.col.f32.f16.f16.f32 "
                 "{%0,%1,%2,%3},{%4,%5,%6,%7},{%8,%9},{%0,%1,%2,%3};"
                 : "+f"(c0), "+f"(c1), "+f"(c2), "+f"(c3)
                 : "r"(a0), "r"(a1), "r"(a2), "r"(a3), "r"(b0), "r"(b1));
}
__device__ __forceinline__ unsigned pack2(float a, float b) {
    __half2 h = __floats2half2_rn(a, b);
    return *(unsigned*)&h;
}
__device__ __forceinline__ void split2(float a, float b, unsigned& hi, unsigned& lo) {
    __half ha = __float2half(a), hb = __float2half(b);
    __half la = __float2half(a - __half2float(ha));
    __half lb = __float2half(b - __half2float(hb));
    __half2 h = __halves2half2(ha, hb), l = __halves2half2(la, lb);
    hi = *(unsigned*)&h; lo = *(unsigned*)&l;
}
// packed fp32 add (exact): acc += cvt(h2) using one add.rn.f32x2
__device__ __forceinline__ void padd2(float2& acc, unsigned h2bits) {
    float2 f = __half22float2(*(__half2*)&h2bits);
    asm("add.rn.f32x2 %0, %0, %1;"
        : "+l"(*reinterpret_cast<unsigned long long*>(&acc))
        : "l"(*reinterpret_cast<const unsigned long long*>(&f)));
}
__device__ __forceinline__ void paddf(float2& acc, float2 f) {
    asm("add.rn.f32x2 %0, %0, %1;"
        : "+l"(*reinterpret_cast<unsigned long long*>(&acc))
        : "l"(*reinterpret_cast<const unsigned long long*>(&f)));
}

// ---------------- kernel 0: setup (init minmax by GLOBAL index + pad row + fp16 cvt) ----------------
__global__ void setup_kernel(float* cmin, float* cmax, __half* te,
                             const float* __restrict__ nodeW, const float* __restrict__ outW,
                             __half* __restrict__ nodeWh, __half* __restrict__ outWh) {
    int i = blockIdx.x * 256 + threadIdx.x;      // 128 blocks x 256 = 32768
    nodeWh[i] = __float2half(nodeW[i]);
    outWh[i]  = __float2half(outW[i]);
    if (i < NH * OD) {                           // global index: blocks 0-1 cover all 512
        cmin[i] =  __int_as_float(0x7f800000);
        cmax[i] = -__int_as_float(0x7f800000);
    }
    if (blockIdx.x == 0 && threadIdx.x < 32)
        ((uint4*)((char*)te + ZERO_OFF))[threadIdx.x] = make_uint4(0u, 0u, 0u, 0u);
}

// ---------------- kernel 1: te via HMMA hi/lo split (R9 proven) ----------------
__global__ __launch_bounds__(256, 1) void te_mma_kernel(
    const float* __restrict__ ef, const float* __restrict__ edgeW,
    const float* __restrict__ edgeB, __half* __restrict__ te) {
    extern __shared__ char smc[];
    __half* sefH = (__half*)(smc);
    __half* sefL = (__half*)(smc + 34816);
    __half* sWH  = (__half*)(smc + 69632);
    __half* sWL  = (__half*)(smc + 137216);

    int t = threadIdx.x, lane = t & 31, w = t >> 5;
    int e0 = blockIdx.x * 128;
    {
        int qg = lane * 4;
#pragma unroll
        for (int i = 0; i < 16; i++) {
            int r = i * 8 + w;
            float4 v = __ldg((const float4*)&ef[(size_t)(e0 + r) * ED + qg]);
            unsigned h0, l0, h1, l1;
            split2(v.x, v.y, h0, l0);
            split2(v.z, v.w, h1, l1);
            *(uint2*)&sefH[r * 136 + qg] = make_uint2(h0, h1);
            *(uint2*)&sefL[r * 136 + qg] = make_uint2(l0, l1);
        }
    }
    {
#pragma unroll
        for (int i = 0; i < 32; i++) {
            int idx4 = i * 256 + t;
            int fidx = idx4 * 4;
            int h = fidx >> 13, k = (fidx >> 6) & 127, c = fidx & 63;
            int n = h * 64 + c;
            float4 v = __ldg((const float4*)&edgeW[fidx]);
            unsigned h0, l0, h1, l1;
            split2(v.x, v.y, h0, l0);
            split2(v.z, v.w, h1, l1);
            *(uint2*)&sWH[k * 264 + n] = make_uint2(h0, h1);
            *(uint2*)&sWL[k * 264 + n] = make_uint2(l0, l1);
        }
    }
    __syncthreads();

    int mw = w >> 2, nwp = w & 3;
    int g = lane >> 2, tig = lane & 3;
    int m0 = mw * 64, nb = nwp * 64;
    const __half* aP[3] = { sefH, sefH, sefL };
    const __half* bP[3] = { sWH,  sWL,  sWH  };

#pragma unroll
    for (int msub = 0; msub < 64; msub += 16) {
        float acc[8][4];
#pragma unroll
        for (int j = 0; j < 8; j++)
#pragma unroll
            for (int q = 0; q < 4; q++) acc[j][q] = 0.f;
#pragma unroll
        for (int pass = 0; pass < 3; pass++) {
            unsigned aBase = smem_u32(aP[pass]) +
                (unsigned)(((m0 + msub + (lane & 15)) * 136 + (lane >> 4) * 8) * 2);
            unsigned bBase = smem_u32(bP[pass]) +
                (unsigned)((((lane & 15)) * 264 + nb + (lane >> 4) * 8) * 2);
#pragma unroll
            for (int kk = 0; kk < 8; kk++) {
                int k0 = kk * 16;
                unsigned a0, a1, a2, a3;
                ldm_x4(aBase + k0 * 2, a0, a1, a2, a3);
#pragma unroll
                for (int s2 = 0; s2 < 4; s2++) {
                    unsigned b0, b1, b2, b3;
                    ldm_x4t(bBase + (k0 * 264 + s2 * 16) * 2, b0, b1, b2, b3);
                    mma16816(acc[s2 * 2][0], acc[s2 * 2][1], acc[s2 * 2][2], acc[s2 * 2][3],
                             a0, a1, a2, a3, b0, b1);
                    mma16816(acc[s2 * 2 + 1][0], acc[s2 * 2 + 1][1], acc[s2 * 2 + 1][2],
                             acc[s2 * 2 + 1][3], a0, a1, a2, a3, b2, b3);
                }
            }
        }
#pragma unroll
        for (int j = 0; j < 8; j++) {
            int cb = nb + j * 8 + tig * 2;
            float b0 = __ldg(&edgeB[cb]);
            float b1 = __ldg(&edgeB[cb + 1]);
            int r0 = e0 + m0 + msub + g;
            *(__half2*)&te[(size_t)r0 * 256 + cb] =
                __floats2half2_rn(acc[j][0] + b0, acc[j][1] + b1);
            *(__half2*)&te[(size_t)(r0 + 8) * 256 + cb] =
                __floats2half2_rn(acc[j][2] + b0, acc[j][3] + b1);
        }
    }
}

// ---------------- kernel 2: scan — R13 gather + round-robin quad distribution ----------------
__global__ void scan_kernel(const float* __restrict__ inc, const __half* __restrict__ te,
                            __half* __restrict__ agg) {
    __shared__ int s_idx[516];
    __shared__ int s_wcnt[8];
    __shared__ float4 sxch[192];
    int t = threadIdx.x, w = t >> 5, l = t & 31;
    int n = blockIdx.x;

    const float4* row = (const float4*)(inc + (size_t)n * N_EDGES);
    unsigned mask = 0u;
#pragma unroll
    for (int i = 0; i < 8; i++) {
        float4 v = __ldcs(row + i * 256 + t);
        unsigned m = (v.x != 0.f ? 1u : 0u) | (v.y != 0.f ? 2u : 0u) |
                     (v.z != 0.f ? 4u : 0u) | (v.w != 0.f ? 8u : 0u);
        mask |= m << (i * 4);
    }
    int myc = __popc(mask);
    int pre = myc;
#pragma unroll
    for (int d = 1; d < 32; d <<= 1) {
        int o = __shfl_up_sync(0xffffffffu, pre, d);
        if (l >= d) pre += o;
    }
    int wtot = __shfl_sync(0xffffffffu, pre, 31);
    int myoff = pre - myc;
    if (l == 0) s_wcnt[w] = wtot;
    __syncthreads();

    int base = 0, cnt = 0;
#pragma unroll
    for (int w2 = 0; w2 < 8; w2++) {
        int c2 = s_wcnt[w2];
        if (w2 < w) base += c2;
        cnt += c2;
    }
    int pos = base + myoff;
    unsigned mm = mask;
    while (mm) {
        int b = __ffs(mm) - 1;
        mm &= mm - 1;
        s_idx[pos++] = (((b >> 2) * 256 + t) * 4 + (b & 3)) << 9;  // byte offset
    }
    int padded = (cnt + 3) & ~3;                  // <=3 pad entries -> zero row
    if (t < padded - cnt) s_idx[cnt + t] = ZERO_OFF;
    __syncthreads();

    float inv = 1.f / ((float)cnt + EPSV);
    int nquads = padded >> 2;

    // gather: group q (0..3) takes quads q, q+4, ...; 64 col-threads x 8B each
    int q = t >> 6, c4 = t & 63;
    const char* teB = (const char*)te + c4 * 8;
    float2 a01A = make_float2(0.f, 0.f), a23A = a01A;
    float2 a01B = a01A, a23B = a01A;
    for (int qd = q; qd < nquads; qd += 4) {
        int4 ix = *(const int4*)&s_idx[qd * 4];   // one LDS.128 = 4 byte-offsets
        uint2 v0 = __ldg((const uint2*)(teB + ix.x));
        uint2 v1 = __ldg((const uint2*)(teB + ix.y));
        uint2 v2 = __ldg((const uint2*)(teB + ix.z));
        uint2 v3 = __ldg((const uint2*)(teB + ix.w));
        padd2(a01A, v0.x); padd2(a23A, v0.y);
        padd2(a01B, v1.x); padd2(a23B, v1.y);
        padd2(a01A, v2.x); padd2(a23A, v2.y);
        padd2(a01B, v3.x); padd2(a23B, v3.y);
    }
    paddf(a01A, a01B);
    paddf(a23A, a23B);
    float4 acc = make_float4(a01A.x, a01A.y, a23A.x, a23A.y);
    __syncthreads();
    if (q != 0) sxch[(q - 1) * 64 + c4] = acc;
    __syncthreads();
    if (q == 0) {
        float4 b1 = sxch[c4], b2 = sxch[64 + c4], b3 = sxch[128 + c4];
        acc.x = (acc.x + b1.x + b2.x + b3.x) * inv;
        acc.y = (acc.y + b1.y + b2.y + b3.y) * inv;
        acc.z = (acc.z + b1.z + b2.z + b3.z) * inv;
        acc.w = (acc.w + b1.w + b2.w + b3.w) * inv;
        *(uint2*)&agg[(size_t)n * 256 + c4 * 4] =
            make_uint2(pack2(acc.x, acc.y), pack2(acc.z, acc.w));
    }
}

// ---------------- kernel 3: HMMA fused head (R7/R9 proven) ----------------
__global__ __launch_bounds__(256, 2) void head_kernel(
    const float* __restrict__ x, const __half* __restrict__ agg,
    const __half* __restrict__ nodeWh, const float* __restrict__ nodeB,
    const float* __restrict__ attnW, const float* __restrict__ attnB,
    const __half* __restrict__ outWh, const float* __restrict__ outB,
    int h, float* __restrict__ upd,
    float* __restrict__ cmin, float* __restrict__ cmax,
    const float* __restrict__ pmin, const float* __restrict__ pmax) {
    extern __shared__ char smc[];
    __half* sxh  = (__half*)(smc);
    __half* swh  = (__half*)(smc + 34816);
    __half* stn  = (__half*)(smc + 53248);
    __half* sagg = (__half*)(smc + 71680);
    float* sattn = (float*)(smc + 90112);
    float* sg    = (float*)(smc + 90368);
    float* smin  = (float*)(smc + 90880);
    float* smax  = (float*)(smc + 92928);

    int t = threadIdx.x, lane = t & 31, w = t >> 5;
    int n0 = blockIdx.x * 128;
    bool dn = (pmin != nullptr);

    {
        int qg = lane * 4;
        float sa4[4], sb4[4];
        if (dn) {
#pragma unroll
            for (int j = 0; j < 4; j++) {
                float mn = __ldg(&pmin[qg + j]), mx = __ldg(&pmax[qg + j]);
                sb4[j] = mn; sa4[j] = 1.f / (mx - mn + EPSV);
            }
        }
#pragma unroll
        for (int i = 0; i < 16; i++) {
            int r = i * 8 + w;
            float4 v = __ldg((const float4*)&x[(size_t)(n0 + r) * ND + qg]);
            if (dn) {
                v.x = fmaxf(0.f, (v.x - sb4[0]) * sa4[0]);
                v.y = fmaxf(0.f, (v.y - sb4[1]) * sa4[1]);
                v.z = fmaxf(0.f, (v.z - sb4[2]) * sa4[2]);
                v.w = fmaxf(0.f, (v.w - sb4[3]) * sa4[3]);
            }
            *(uint2*)&sxh[r * 136 + qg] = make_uint2(pack2(v.x, v.y), pack2(v.z, v.w));
        }
    }
    {
        const __half* nw = nodeWh + h * (ND * HD);
#pragma unroll
        for (int i = 0; i < 4; i++) {
            int idx = i * 256 + t;
            int k = idx >> 3, n8 = (idx & 7) * 8;
            *(uint4*)&swh[k * 72 + n8] = __ldg((const uint4*)&nw[idx * 8]);
        }
    }
    {
        int c8 = (t & 7) * 8;
#pragma unroll
        for (int i = 0; i < 4; i++) {
            int r = i * 32 + (t >> 3);
            *(uint4*)&sagg[r * 72 + c8] =
                __ldg((const uint4*)&agg[(size_t)(n0 + r) * 256 + h * 64 + c8]);
        }
    }
    if (t < 64) sattn[t] = attnW[h * 64 + t];
    __syncthreads();

    int mw = w >> 1, nwp = w & 1;
    int g = lane >> 2, tig = lane & 3;

    {
        int m0 = mw * 32, nb = nwp * 32;
#pragma unroll
        for (int msub = 0; msub < 32; msub += 16) {
            float acc[4][4];
#pragma unroll
            for (int j = 0; j < 4; j++)
#pragma unroll
                for (int q = 0; q < 4; q++) acc[j][q] = 0.f;

            unsigned aBase = smem_u32(sxh) +
                (unsigned)(((m0 + msub + (lane & 15)) * 136 + (lane >> 4) * 8) * 2);
            unsigned bBase = smem_u32(swh) +
                (unsigned)((((lane & 15)) * 72 + nb + (lane >> 4) * 8) * 2);
#pragma unroll
            for (int kk = 0; kk < 8; kk++) {
                int k0 = kk * 16;
                unsigned a0, a1, a2, a3, b0, b1, b2, b3, b4, b5, b6, b7;
                ldm_x4(aBase + k0 * 2, a0, a1, a2, a3);
                ldm_x4t(bBase + k0 * 72 * 2, b0, b1, b2, b3);
                ldm_x4t(bBase + k0 * 72 * 2 + 32, b4, b5, b6, b7);
                mma16816(acc[0][0], acc[0][1], acc[0][2], acc[0][3], a0, a1, a2, a3, b0, b1);
                mma16816(acc[1][0], acc[1][1], acc[1][2], acc[1][3], a0, a1, a2, a3, b2, b3);
                mma16816(acc[2][0], acc[2][1], acc[2][2], acc[2][3], a0, a1, a2, a3, b4, b5);
                mma16816(acc[3][0], acc[3][1], acc[3][2], acc[3][3], a0, a1, a2, a3, b6, b7);
            }
#pragma unroll
            for (int j = 0; j < 4; j++) {
                int cb = nb + j * 8 + tig * 2;
                float nb0 = __ldg(&nodeB[h * 64 + cb]);
                float nb1 = __ldg(&nodeB[h * 64 + cb + 1]);
                int rr = m0 + msub + g;
                stn[rr * 72 + cb]           = __float2half(acc[j][0] + nb0);
                stn[rr * 72 + cb + 1]       = __float2half(acc[j][1] + nb1);
                stn[(rr + 8) * 72 + cb]     = __float2half(acc[j][2] + nb0);
                stn[(rr + 8) * 72 + cb + 1] = __float2half(acc[j][3] + nb1);
            }
        }
    }
    __syncthreads();

    {
        int r = w * 16 + (lane >> 1);
        int sub = lane & 1;
        float s = 0.f;
#pragma unroll
        for (int cc = 0; cc < 32; cc++) {
            int c = sub * 32 + cc;
            s += (__half2float(stn[r * 72 + c]) + __half2float(sagg[r * 72 + c])) * sattn[c];
        }
        s += __shfl_xor_sync(0xffffffffu, s, 1);
        if (sub == 0) {
            s += attnB[h];
            s = (s >= 0.f) ? s : 0.2f * s;
            sg[r] = 1.f / (1.f + expf(-s));
        }
    }
    {
        const __half* ow = outWh + h * (HD * OD);
#pragma unroll
        for (int i = 0; i < 4; i++) {
            int idx = i * 256 + t;
            int k = idx >> 4, n8 = (idx & 15) * 8;
            *(uint4*)&swh[k * 136 + n8] = __ldg((const uint4*)&ow[idx * 8]);
        }
    }
    __syncthreads();

#pragma unroll
    for (int i = 0; i < 16; i++) {
        int L = i * 256 + t;
        int r = L >> 5, c2 = (L & 31) * 2;
        float gv = sg[r];
        float2 av = __half22float2(*(__half2*)&sagg[r * 72 + c2]);
        float2 tv = __half22float2(*(__half2*)&stn[r * 72 + c2]);
        *(__half2*)&stn[r * 72 + c2] = __floats2half2_rn(gv * av.x + tv.x, gv * av.y + tv.y);
    }
    __syncthreads();

    {
        int m0 = mw * 32, nb = nwp * 64;
        float mnA[8], mxA[8], mnB[8], mxB[8];
#pragma unroll
        for (int j = 0; j < 8; j++) {
            mnA[j] = 3.4e38f; mxA[j] = -3.4e38f;
            mnB[j] = 3.4e38f; mxB[j] = -3.4e38f;
        }
#pragma unroll
        for (int msub = 0; msub < 32; msub += 16) {
            float acc[8][4];
#pragma unroll
            for (int j = 0; j < 8; j++)
#pragma unroll
                for (int q = 0; q < 4; q++) acc[j][q] = 0.f;

            unsigned aBase = smem_u32(stn) +
                (unsigned)(((m0 + msub + (lane & 15)) * 72 + (lane >> 4) * 8) * 2);
            unsigned bBase = smem_u32(swh) +
                (unsigned)((((lane & 15)) * 136 + nb + (lane >> 4) * 8) * 2);
#pragma unroll
            for (int kk = 0; kk < 4; kk++) {
                int k0 = kk * 16;
                unsigned a0, a1, a2, a3;
                ldm_x4(aBase + k0 * 2, a0, a1, a2, a3);
#pragma unroll
                for (int s2 = 0; s2 < 4; s2++) {
                    unsigned b0, b1, b2, b3;
                    ldm_x4t(bBase + (k0 * 136 + s2 * 16) * 2, b0, b1, b2, b3);
                    mma16816(acc[s2 * 2][0], acc[s2 * 2][1], acc[s2 * 2][2], acc[s2 * 2][3],
                             a0, a1, a2, a3, b0, b1);
                    mma16816(acc[s2 * 2 + 1][0], acc[s2 * 2 + 1][1], acc[s2 * 2 + 1][2],
                             acc[s2 * 2 + 1][3], a0, a1, a2, a3, b2, b3);
                }
            }
#pragma unroll
            for (int j = 0; j < 8; j++) {
                int cb = nb + j * 8 + tig * 2;
                float ob0 = __ldg(&outB[h * 128 + cb]);
                float ob1 = __ldg(&outB[h * 128 + cb + 1]);
                float o00 = acc[j][0] + ob0, o01 = acc[j][1] + ob1;
                float o10 = acc[j][2] + ob0, o11 = acc[j][3] + ob1;
                int r0g = n0 + m0 + msub + g;
                *(float2*)&upd[(size_t)r0g * OD + cb]       = make_float2(o00, o01);
                *(float2*)&upd[(size_t)(r0g + 8) * OD + cb] = make_float2(o10, o11);
                mnA[j] = fminf(mnA[j], fminf(o00, o10)); mxA[j] = fmaxf(mxA[j], fmaxf(o00, o10));
                mnB[j] = fminf(mnB[j], fminf(o01, o11)); mxB[j] = fmaxf(mxB[j], fmaxf(o01, o11));
            }
        }
#pragma unroll
        for (int d = 4; d <= 16; d <<= 1) {
#pragma unroll
            for (int j = 0; j < 8; j++) {
                mnA[j] = fminf(mnA[j], __shfl_xor_sync(0xffffffffu, mnA[j], d));
                mxA[j] = fmaxf(mxA[j], __shfl_xor_sync(0xffffffffu, mxA[j], d));
                mnB[j] = fminf(mnB[j], __shfl_xor_sync(0xffffffffu, mnB[j], d));
                mxB[j] = fmaxf(mxB[j], __shfl_xor_sync(0xffffffffu, mxB[j], d));
            }
        }
        if (lane < 4) {
#pragma unroll
            for (int j = 0; j < 8; j++) {
                int cb = nb + j * 8 + tig * 2;
                smin[mw * 128 + cb]     = mnA[j];
                smin[mw * 128 + cb + 1] = mnB[j];
                smax[mw * 128 + cb]     = mxA[j];
                smax[mw * 128 + cb + 1] = mxB[j];
            }
        }
    }
    __syncthreads();
    if (t < 128) {
        float m = smin[t], M = smax[t];
#pragma unroll
        for (int r = 1; r < 4; r++) {
            m = fminf(m, smin[r * 128 + t]);
            M = fmaxf(M, smax[r * 128 + t]);
        }
        atomicMinF(&cmin[t], m);
        atomicMaxF(&cmax[t], M);
    }
}

// ---------------- kernel 4: final norm ----------------
__global__ void norm_kernel(const float4* __restrict__ upd, const float* __restrict__ cmin,
                            const float* __restrict__ cmax, float4* __restrict__ dst) {
    __shared__ float sa[128], sb[128];
    int t = threadIdx.x;
    if (t < 128) {
        float mn = cmin[t], mx = cmax[t];
        sa[t] = 1.f / (mx - mn + EPSV);
        sb[t] = mn;
    }
    __syncthreads();
    int i = blockIdx.x * 256 + t;
    float4 v = upd[i];
    int c = (i & 31) * 4;
    float4 o;
    o.x = fmaxf(0.f, (v.x - sb[c + 0]) * sa[c + 0]);
    o.y = fmaxf(0.f, (v.y - sb[c + 1]) * sa[c + 1]);
    o.z = fmaxf(0.f, (v.z - sb[c + 2]) * sa[c + 2]);
    o.w = fmaxf(0.f, (v.w - sb[c + 3]) * sa[c + 3]);
    dst[i] = o;
}

// ---------------- launch ----------------
extern "C" void kernel_launch(void* const* d_in, const int* in_sizes, int n_in,
                              void* d_out, int out_size) {
    const float* nodeF = (const float*)d_in[0];
    const float* inc   = (const float*)d_in[1];
    const float* edgeF = (const float*)d_in[2];
    const float* nodeW = (const float*)d_in[3];
    const float* nodeB = (const float*)d_in[4];
    const float* edgeW = (const float*)d_in[5];
    const float* edgeB = (const float*)d_in[6];
    const float* attnW = (const float*)d_in[7];
    const float* attnB = (const float*)d_in[8];
    const float* outW  = (const float*)d_in[9];
    const float* outB  = (const float*)d_in[10];

    __half *te, *agg, *nodeWh, *outWh;  float *bufA, *bufB, *cmin, *cmax;
    cudaGetSymbolAddress((void**)&te,     g_te);
    cudaGetSymbolAddress((void**)&agg,    g_agg);
    cudaGetSymbolAddress((void**)&nodeWh, g_nodeWh);
    cudaGetSymbolAddress((void**)&outWh,  g_outWh);
    cudaGetSymbolAddress((void**)&bufA,   g_bufA);
    cudaGetSymbolAddress((void**)&bufB,   g_bufB);
    cudaGetSymbolAddress((void**)&cmin,   g_cmin);
    cudaGetSymbolAddress((void**)&cmax,   g_cmax);

    const int hk_smem = 94976;
    const int te_smem = 204800;
    cudaFuncSetAttribute(head_kernel, cudaFuncAttributeMaxDynamicSharedMemorySize, hk_smem);
    cudaFuncSetAttribute(te_mma_kernel, cudaFuncAttributeMaxDynamicSharedMemorySize, te_smem);

    setup_kernel<<<NH * ND * HD / 256, 256>>>(cmin, cmax, te, nodeW, outW, nodeWh, outWh);
    te_mma_kernel<<<N_EDGES / 128, 256, te_smem>>>(edgeF, edgeW, edgeB, te);
    scan_kernel<<<N_NODES, 256>>>(inc, te, agg);

    float* bufs[2] = { bufA, bufB };
    const float* xin = nodeF;
    for (int h = 0; h < NH; h++) {
        float* dst = bufs[h & 1];
        const float* pmin = (h == 0) ? nullptr : cmin + (h - 1) * 128;
        const float* pmax = (h == 0) ? nullptr : cmax + (h - 1) * 128;
        head_kernel<<<N_NODES / 128, 256, hk_smem>>>(xin, agg, nodeWh, nodeB, attnW, attnB,
                                                     outWh, outB, h, dst,
                                                     cmin + h * 128, cmax + h * 128,
                                                     pmin, pmax);
        xin = dst;
    }
    norm_kernel<<<(N_NODES * OD / 4) / 256, 256>>>((const float4*)bufs[(NH - 1) & 1],
                                                   cmin + (NH - 1) * 128, cmax + (NH - 1) * 128,
                                                   (float4*)d_out);
}